// round 9
// baseline (speedup 1.0000x reference)
#include <cuda_runtime.h>
#include <cstdint>
#include <math.h>

// Problem dims (fixed by the dataset problem)
#define BB   8
#define TT   100
#define SS   128
#define FF   768
#define SF   (SS * FF)          // 98304
#define BSF  (BB * SF)          // 786432
#define TSF  (TT * SF)          // 9830400
#define NTOT (BB * TSF)         // 78643200  (elements per stacked half)

// Packed per-(b,s,f) word:
//   bits[9:32) = thresh = ceil(p * 2^23)   (rate:  spike <=> bits32 < thresh<<9)
//   bits[0:9)  = tm = (int)(p * 10.f)      (temporal spike time, 0..10)
__device__ uint32_t g_w32[BSF];

// Rotation powers 2^R loaded at runtime so ptxas cannot strength-reduce the
// wide multiply back into SHF (IMAD.WIDE must land on the fma pipe).
__device__ __align__(16) uint32_t g_rotc[4] = {
    1u << 13, 1u << 26, 1u << 17, 1u << 16
};

// ---------------------------------------------------------------------------
// Correctly-rounded f32 sigmoid via double-single arithmetic on the fp32 pipe
// (bit-compatible with the f64 path per R6: rel_err == 0.0).
// ---------------------------------------------------------------------------
__device__ __forceinline__ float sigmoid_cr(float x) {
    if (fabsf(x) > 20.0f) {
        double pd = 1.0 / (1.0 + exp(-(double)x));
        return (float)pd;
    }
    const float L2E_HI = 1.4426950216293335f;
    const float L2E_LO = 1.9259629911266175e-8f;
    float xn  = -x;
    float thi = xn * L2E_HI;
    float tlo = fmaf(xn, L2E_HI, -thi);
    tlo = fmaf(xn, L2E_LO, tlo);
    float n   = rintf(thi);
    float fhi = thi - n;
    const float LN2_HI = 0.6931471824645996f;
    const float LN2_LO = -1.904654323148236e-9f;
    float uhi = fhi * LN2_HI;
    float ulo = fmaf(fhi, LN2_HI, -uhi);
    ulo = fmaf(fhi, LN2_LO, ulo);
    ulo = fmaf(tlo, LN2_HI, ulo);
    float q;
    q = fmaf(2.4801587e-5f, uhi, 1.9841270e-4f);
    q = fmaf(q, uhi, 1.3888889e-3f);
    q = fmaf(q, uhi, 8.3333338e-3f);
    q = fmaf(q, uhi, 4.1666668e-2f);
    q = fmaf(q, uhi, 1.6666667e-1f);
    q = fmaf(q, uhi, 0.5f);
    float u2 = uhi * uhi;
    float v  = u2 * q;
    float c  = fmaf(ulo, uhi, ulo);
    float shi = 1.0f + uhi;
    float slo = uhi - (shi - 1.0f);
    float ehi = shi + v;
    float elo = (v - (ehi - shi)) + slo + c;
    int   ni = (int)n;
    float sc = __int_as_float((ni + 127) << 23);
    ehi *= sc;
    elo *= sc;
    float dhi = 1.0f + ehi;
    float t1  = dhi - 1.0f;
    float dlo = ((1.0f - (dhi - t1)) + (ehi - t1)) + elo;
    float r   = 1.0f / dhi;
    float res = fmaf(r, dhi, -1.0f);
    res = fmaf(r, dlo, res);
    return fmaf(-r, res, r);
}

// ---------------------------------------------------------------------------
// Prep: pack threshold<<9 | time per (b,s,f).
// ---------------------------------------------------------------------------
__global__ void __launch_bounds__(256) prep_kernel(const float* __restrict__ feat) {
    int i = blockIdx.x * blockDim.x + threadIdx.x;
    if (i >= BSF) return;
    float p = sigmoid_cr(feat[i]);
    uint32_t thresh = (uint32_t)ceilf(p * 8388608.0f);   // ceil(p * 2^23)
    uint32_t tm = (uint32_t)(int)(p * 10.0f);            // JAX: int32(p * 10)
    uint32_t w;
    if (thresh >= 0x800000u) w = 0xFFFFFFFFu;
    else                     w = (thresh << 9) | tm;
    g_w32[i] = w;
}

// Rotate-left via wide multiply by a runtime 2^R: IMAD.WIDE (fma pipe);
// the (lo|hi)^x0 consumer fuses into one 3-input LOP3 (alu pipe).
__device__ __forceinline__ uint32_t rotw(uint32_t x, uint32_t c) {
    uint64_t p;
    asm("mul.wide.u32 %0, %1, %2;" : "=l"(p) : "r"(x), "r"(c));
    return (uint32_t)p | (uint32_t)(p >> 32);
}

// ---------------------------------------------------------------------------
// JAX partitionable threefry2x32, key (0,42), counter (0, i), out = x0^x1.
// Key schedule FOLDED into the round adds:
//   - init: x0 = 0+ks0 = 0, so round-1's x0+=x1 is a register alias (free)
//   - x0-injections (ks1/ks2/0/ks1/ks2) fold into the following round's
//     x0 = x0 + x1 + K  (single 3-input IADD3); final one folds into output.
//   - x1-injections stay explicit (folding into IMAD.WIDE's addend is WRONG:
//     the 33-bit carry corrupts the rotated hi word).
// ks0=0, ks1=42, ks2=0x1BD11BDA^42=0x1BD11BF0.
// ~69 issue slots/elem vs ~75 before.
// ---------------------------------------------------------------------------
__device__ __forceinline__ uint32_t threefry_bits(uint32_t i, uint32_t c13,
                                                  uint32_t c26, uint32_t c17,
                                                  uint32_t c16) {
    uint32_t x1 = i + 42u;                               // counter lo + ks1
    uint32_t x0 = x1;                                    // round 1: 0 + x1
    x1 = rotw(x1, c13) ^ x0;                             // r1  (w13)
    x0 += x1; x1 = __funnelshift_l(x1, x1, 15) ^ x0;     // r2  (s15)
    x0 += x1; x1 = rotw(x1, c26) ^ x0;                   // r3  (w26)
    x0 += x1; x1 = __funnelshift_l(x1, x1, 6)  ^ x0;     // r4  (s6)
    x1 += 0x1BD11BF1u;                                   // inj1: x1 += ks2+1
    x0 = x0 + x1 + 42u;                                  // r5 add + (x0 += ks1)
    x1 = rotw(x1, c17) ^ x0;                             // r5  (w17)
    x0 += x1; x1 = __funnelshift_l(x1, x1, 29) ^ x0;     // r6  (s29)
    x0 += x1; x1 = rotw(x1, c16) ^ x0;                   // r7  (w16)
    x0 += x1; x1 = __funnelshift_l(x1, x1, 24) ^ x0;     // r8  (s24)
    x1 += 2u;                                            // inj2: x1 += ks0+2
    x0 = x0 + x1 + 0x1BD11BF0u;                          // r9 add + (x0 += ks2)
    x1 = rotw(x1, c13) ^ x0;                             // r9  (w13)
    x0 += x1; x1 = __funnelshift_l(x1, x1, 15) ^ x0;     // r10 (s15)
    x0 += x1; x1 = rotw(x1, c26) ^ x0;                   // r11 (w26)
    x0 += x1; x1 = __funnelshift_l(x1, x1, 6)  ^ x0;     // r12 (s6)
    x1 += 45u;                                           // inj3: x1 += ks1+3
    x0 = x0 + x1;                                        // r13 add (x0 += ks0 = 0)
    x1 = rotw(x1, c17) ^ x0;                             // r13 (w17)
    x0 += x1; x1 = __funnelshift_l(x1, x1, 29) ^ x0;     // r14 (s29)
    x0 += x1; x1 = rotw(x1, c16) ^ x0;                   // r15 (w16)
    x0 += x1; x1 = __funnelshift_l(x1, x1, 24) ^ x0;     // r16 (s24)
    x1 += 0x1BD11BF4u;                                   // inj4: x1 += ks2+4
    x0 = x0 + x1 + 42u;                                  // r17 add + (x0 += ks1)
    x1 = rotw(x1, c13) ^ x0;                             // r17 (w13)
    x0 += x1; x1 = __funnelshift_l(x1, x1, 15) ^ x0;     // r18 (s15)
    x0 += x1; x1 = rotw(x1, c26) ^ x0;                   // r19 (w26)
    x0 += x1; x1 = __funnelshift_l(x1, x1, 6)  ^ x0;     // r20 (s6)
    // final injection folded into the combine:
    return (x0 + 0x1BD11BF0u) ^ (x1 + 5u);               // (x0+ks2)^(x1+ks0+5)
}

// ---------------------------------------------------------------------------
// Fused kernel (R6 shape: 4 elems/thread, 1D grid — best measured).
// g_w32 (3 MB) stays L2-resident, reused T=100 times.
// ---------------------------------------------------------------------------
__global__ void __launch_bounds__(256) spike_kernel(float* __restrict__ out) {
    uint32_t tid = blockIdx.x * blockDim.x + threadIdx.x;
    uint32_t j0  = tid * 4u;                  // < NTOT, multiple of 4

    // Runtime rotation constants (one LDG.128, L2-resident, opaque to ptxas)
    const uint4 rc = *reinterpret_cast<const uint4*>(g_rotc);
    const uint32_t c13 = rc.x, c26 = rc.y, c17 = rc.z, c16 = rc.w;

    uint32_t b   = j0 / TSF;                  // batch 0..7
    uint32_t rem = j0 - b * TSF;
    uint32_t t   = rem / SF;                  // timestep 0..99
    uint32_t sf  = rem - t * SF;              // s*F + f, multiple of 4

    const uint4 wv = *reinterpret_cast<const uint4*>(&g_w32[b * SF + sf]);
    const uint32_t w[4] = {wv.x, wv.y, wv.z, wv.w};

    uint32_t bits[4];
#pragma unroll
    for (int k = 0; k < 4; ++k)
        bits[k] = threefry_bits(j0 + (uint32_t)k, c13, c26, c17, c16);

    float rate[4];
#pragma unroll
    for (int k = 0; k < 4; ++k)
        rate[k] = (bits[k] < w[k]) ? 1.0f : 0.0f;

    *reinterpret_cast<float4*>(out + j0) =
        make_float4(rate[0], rate[1], rate[2], rate[3]);

    float4 tv;
    if (t <= 10u) {                            // warp-uniform branch
        tv.x = ((w[0] & 511u) == t) ? 1.0f : 0.0f;
        tv.y = ((w[1] & 511u) == t) ? 1.0f : 0.0f;
        tv.z = ((w[2] & 511u) == t) ? 1.0f : 0.0f;
        tv.w = ((w[3] & 511u) == t) ? 1.0f : 0.0f;
    } else {
        tv = make_float4(0.0f, 0.0f, 0.0f, 0.0f);
    }
    *reinterpret_cast<float4*>(out + (uint32_t)NTOT + j0) = tv;
}

extern "C" void kernel_launch(void* const* d_in, const int* in_sizes, int n_in,
                              void* d_out, int out_size) {
    const float* features = (const float*)d_in[0];
    float* out = (float*)d_out;

    // 786432 / 256 = 3072 blocks (exact)
    prep_kernel<<<BSF / 256, 256>>>(features);

    // NTOT/4 threads = 19,660,800 / 256 = 76,800 blocks (exact)
    spike_kernel<<<(NTOT / 4) / 256, 256>>>(out);
}

// round 10
// speedup vs baseline: 1.0382x; 1.0382x over previous
#include <cuda_runtime.h>
#include <cstdint>
#include <math.h>

// Problem dims (fixed by the dataset problem)
#define BB   8
#define TT   100
#define SS   128
#define FF   768
#define SF   (SS * FF)          // 98304
#define BSF  (BB * SF)          // 786432
#define TSF  (TT * SF)          // 9830400
#define NTOT (BB * TSF)         // 78643200  (elements per stacked half)

// Blocks: each covers 1024 consecutive elements of one (b,t) row.
#define BLKS_PER_ROW  (SF / 1024)        // 96
#define ROWS          (BB * TT)          // 800

// Packed per-(b,s,f) word:
//   bits[9:32) = thresh = ceil(p * 2^23)   (rate:  spike <=> bits32 < thresh<<9)
//   bits[0:9)  = tm = (int)(p * 10.f)      (temporal spike time, 0..10)
__device__ uint32_t g_w32[BSF];

// ---------------------------------------------------------------------------
// Correctly-rounded f32 sigmoid via double-single arithmetic on the fp32 pipe
// (bit-compatible with the f64 path per R6-R9: rel_err == 0.0).
// ---------------------------------------------------------------------------
__device__ __forceinline__ float sigmoid_cr(float x) {
    if (fabsf(x) > 20.0f) {
        double pd = 1.0 / (1.0 + exp(-(double)x));
        return (float)pd;
    }
    const float L2E_HI = 1.4426950216293335f;
    const float L2E_LO = 1.9259629911266175e-8f;
    float xn  = -x;
    float thi = xn * L2E_HI;
    float tlo = fmaf(xn, L2E_HI, -thi);
    tlo = fmaf(xn, L2E_LO, tlo);
    float n   = rintf(thi);
    float fhi = thi - n;
    const float LN2_HI = 0.6931471824645996f;
    const float LN2_LO = -1.904654323148236e-9f;
    float uhi = fhi * LN2_HI;
    float ulo = fmaf(fhi, LN2_HI, -uhi);
    ulo = fmaf(fhi, LN2_LO, ulo);
    ulo = fmaf(tlo, LN2_HI, ulo);
    float q;
    q = fmaf(2.4801587e-5f, uhi, 1.9841270e-4f);
    q = fmaf(q, uhi, 1.3888889e-3f);
    q = fmaf(q, uhi, 8.3333338e-3f);
    q = fmaf(q, uhi, 4.1666668e-2f);
    q = fmaf(q, uhi, 1.6666667e-1f);
    q = fmaf(q, uhi, 0.5f);
    float u2 = uhi * uhi;
    float v  = u2 * q;
    float c  = fmaf(ulo, uhi, ulo);
    float shi = 1.0f + uhi;
    float slo = uhi - (shi - 1.0f);
    float ehi = shi + v;
    float elo = (v - (ehi - shi)) + slo + c;
    int   ni = (int)n;
    float sc = __int_as_float((ni + 127) << 23);
    ehi *= sc;
    elo *= sc;
    float dhi = 1.0f + ehi;
    float t1  = dhi - 1.0f;
    float dlo = ((1.0f - (dhi - t1)) + (ehi - t1)) + elo;
    float r   = 1.0f / dhi;
    float res = fmaf(r, dhi, -1.0f);
    res = fmaf(r, dlo, res);
    return fmaf(-r, res, r);
}

// ---------------------------------------------------------------------------
// Prep: pack threshold<<9 | time per (b,s,f).
// ---------------------------------------------------------------------------
__global__ void __launch_bounds__(256) prep_kernel(const float* __restrict__ feat) {
    int i = blockIdx.x * blockDim.x + threadIdx.x;
    if (i >= BSF) return;
    float p = sigmoid_cr(feat[i]);
    uint32_t thresh = (uint32_t)ceilf(p * 8388608.0f);   // ceil(p * 2^23)
    uint32_t tm = (uint32_t)(int)(p * 10.0f);            // JAX: int32(p * 10)
    uint32_t w;
    if (thresh >= 0x800000u) w = 0xFFFFFFFFu;
    else                     w = (thresh << 9) | tm;
    g_w32[i] = w;
}

// ---------------------------------------------------------------------------
// JAX partitionable threefry2x32: per-element 64-bit counter (hi=0, lo=i),
// key = (0, 42), output = x0_final ^ x1_final.  All-SHF form: minimum
// instruction count (slot-count is the only lever that moves time; R5/R8/R9
// pipe-rebalance experiments were all neutral).
// ---------------------------------------------------------------------------
__device__ __forceinline__ uint32_t threefry_bits(uint32_t i) {
    const uint32_t ks0 = 0u;
    const uint32_t ks1 = 42u;
    const uint32_t ks2 = 0x1BD11BDAu ^ 0u ^ 42u;
    uint32_t x0 = 0u + ks0;        // counter hi = 0
    uint32_t x1 = i  + ks1;        // counter lo = element index
#define TF_ROUND(r) { x0 += x1; x1 = __funnelshift_l(x1, x1, (r)); x1 ^= x0; }
    TF_ROUND(13) TF_ROUND(15) TF_ROUND(26) TF_ROUND(6)
    x0 += ks1; x1 += ks2 + 1u;
    TF_ROUND(17) TF_ROUND(29) TF_ROUND(16) TF_ROUND(24)
    x0 += ks2; x1 += ks0 + 2u;
    TF_ROUND(13) TF_ROUND(15) TF_ROUND(26) TF_ROUND(6)
    x0 += ks0; x1 += ks1 + 3u;
    TF_ROUND(17) TF_ROUND(29) TF_ROUND(16) TF_ROUND(24)
    x0 += ks1; x1 += ks2 + 4u;
    TF_ROUND(13) TF_ROUND(15) TF_ROUND(26) TF_ROUND(6)
    x0 += ks2; x1 += ks0 + 5u;
#undef TF_ROUND
    return x0 ^ x1;                // partitionable 32-bit combine
}

// ---------------------------------------------------------------------------
// Fused kernel. 1D grid, SAME block count and tid->address mapping as the
// 204us R6 kernel, but (b, t, sf) are derived from blockIdx.x only: the two
// magic-number divisions move off the per-thread slot budget onto the
// uniform datapath (~4 slots/elem saved).
// g_w32 (3 MB) stays L2-resident, reused T=100 times.
// ---------------------------------------------------------------------------
__global__ void __launch_bounds__(256) spike_kernel(float* __restrict__ out) {
    const uint32_t blk   = blockIdx.x;                  // 0..76799
    const uint32_t row   = blk / BLKS_PER_ROW;          // (b*TT + t), uniform
    const uint32_t chunk = blk - row * BLKS_PER_ROW;    // 0..95, uniform
    const uint32_t b     = row / TT;                    // uniform
    const uint32_t t     = row - b * TT;                // uniform

    const uint32_t lane4 = threadIdx.x * 4u;
    const uint32_t sf    = chunk * 1024u + lane4;       // s*F + f, mult of 4
    const uint32_t j0    = blk * 1024u + lane4;         // == b*TSF + t*SF + sf

    const uint4 wv = *reinterpret_cast<const uint4*>(&g_w32[b * SF + sf]);
    const uint32_t w[4] = {wv.x, wv.y, wv.z, wv.w};

    uint32_t bits[4];
#pragma unroll
    for (int k = 0; k < 4; ++k)
        bits[k] = threefry_bits(j0 + (uint32_t)k);

    float rate[4];
#pragma unroll
    for (int k = 0; k < 4; ++k)
        rate[k] = (bits[k] < w[k]) ? 1.0f : 0.0f;

    *reinterpret_cast<float4*>(out + j0) =
        make_float4(rate[0], rate[1], rate[2], rate[3]);

    float4 tv;
    if (t <= 10u) {                            // block-uniform branch
        tv.x = ((w[0] & 511u) == t) ? 1.0f : 0.0f;
        tv.y = ((w[1] & 511u) == t) ? 1.0f : 0.0f;
        tv.z = ((w[2] & 511u) == t) ? 1.0f : 0.0f;
        tv.w = ((w[3] & 511u) == t) ? 1.0f : 0.0f;
    } else {
        tv = make_float4(0.0f, 0.0f, 0.0f, 0.0f);
    }
    *reinterpret_cast<float4*>(out + (uint32_t)NTOT + j0) = tv;
}

extern "C" void kernel_launch(void* const* d_in, const int* in_sizes, int n_in,
                              void* d_out, int out_size) {
    const float* features = (const float*)d_in[0];
    float* out = (float*)d_out;

    // 786432 / 256 = 3072 blocks (exact)
    prep_kernel<<<BSF / 256, 256>>>(features);

    // 76,800 blocks x 256 threads x 4 elems = NTOT (exact), 1D grid
    spike_kernel<<<ROWS * BLKS_PER_ROW, 256>>>(out);
}